// round 13
// baseline (speedup 1.0000x reference)
#include <cuda_runtime.h>
#include <cuda_bf16.h>

// CTC forward, two tasks (PyTorch semantics: blank=0, mean of loss/target_len,
// zero_infinity). One block per (task, batch) = 64 blocks x 128 threads.
//
// Barrier-free skewed wavefront. R9 math exactly (4 slots/thread as
// (mantissa,int-exponent) pairs, no MUFU on the critical path), but the
// per-step __syncthreads is replaced by:
//   - per-warp PRIVATE prob staging (coalesced LDG -> ex2 -> own smem
//     double buffer; 3-step register prefetch pipeline), and
//   - a full-depth write-once volatile ring for the single cross-warp
//     operand (left warp lane31's slot-3), whole-warp broadcast poll,
//     sentinel = mantissa bits != 0 (mantissa always in [1,2)).
// Dependency chain is strictly left->right => deadlock-free.

#define LOG2E 1.4426950408889634f
#define LN2   0.6931471805599453f
#define BATCH 32
#define TMAX  2000
#define NT    128
#define EDEAD (-(1 << 28))
// dynamic smem: sD[TMAX] + ring[4][TMAX] uint2
#define DYNSMEM (TMAX * 4 + 4 * TMAX * 8)

static __device__ float        g_partial[64];
static __device__ unsigned int g_count = 0;

__device__ __forceinline__ float ex2(float x) {
    float y; asm("ex2.approx.f32 %0, %1;" : "=f"(y) : "f"(x)); return y;
}
__device__ __forceinline__ float lg2(float x) {
    float y; asm("lg2.approx.f32 %0, %1;" : "=f"(y) : "f"(x)); return y;
}

__device__ __forceinline__ void upd3(float ma, int ea, float mb, int eb,
                                     float mc, int ec, float p,
                                     float& mo, int& eo) {
    int em = max(ea, max(eb, ec));
    float sa = __int_as_float(max(ea - em + 127, 0) << 23);
    float sb = __int_as_float(max(eb - em + 127, 0) << 23);
    float sc = __int_as_float(max(ec - em + 127, 0) << 23);
    float s  = fmaf(mc, sc, fmaf(mb, sb, ma * sa));   // [1,6)
    float mp = p * s;                                  // normal, >0
    int bb = __float_as_int(mp);
    eo = em + ((bb >> 23) - 127);
    mo = __int_as_float((bb & 0x007FFFFF) | 0x3F800000);
}
__device__ __forceinline__ void upd2(float ma, int ea, float mb, int eb,
                                     float p, float& mo, int& eo) {
    int em = max(ea, eb);
    float sa = __int_as_float(max(ea - em + 127, 0) << 23);
    float sb = __int_as_float(max(eb - em + 127, 0) << 23);
    float s  = fmaf(mb, sb, ma * sa);
    float mp = p * s;
    int bb = __float_as_int(mp);
    eo = em + ((bb >> 23) - 127);
    mo = __int_as_float((bb & 0x007FFFFF) | 0x3F800000);
}
__device__ __forceinline__ float pow2c(int dp127) {
    return __int_as_float(max(dp127, 0) << 23);
}
__device__ __forceinline__ float clamplp(float x) {   // keep ex2 output normal
    return fminf(fmaxf(x, -120.f), 0.f);
}

__global__ void __launch_bounds__(NT, 1)
ctc_forward_kernel(const float* __restrict__ elog, const float* __restrict__ plog,
                   const int* __restrict__ etgt, const int* __restrict__ ptgt,
                   const int* __restrict__ eil,  const int* __restrict__ pil,
                   const int* __restrict__ etl,  const int* __restrict__ ptl,
                   float* __restrict__ out)
{
    extern __shared__ unsigned char dynsmem[];
    float* sD    = reinterpret_cast<float*>(dynsmem);               // [TMAX]
    uint2* sRing = reinterpret_cast<uint2*>(dynsmem + TMAX * 4);    // [4][TMAX]

    __shared__ float sMy[4][2][64];   // per-warp private staged prob rows
    __shared__ float sFm[NT * 4];
    __shared__ int   sFe[NT * 4];
    __shared__ int   sLast;

    const int task = blockIdx.x >> 5;   // 0 = error (C=4), 1 = phoneme (C=64)
    const int b    = blockIdx.x & 31;
    const int tid  = threadIdx.x;
    const int lane = tid & 31;
    const int wid  = tid >> 5;

    const float* logits;
    const int*   targets;
    int C, S, ilen, tlen;
    if (task == 0) {
        C = 4;  S = 50;
        logits  = elog + (size_t)b * TMAX * 4;
        targets = etgt + b * 50;
        ilen = eil[b]; tlen = etl[b];
    } else {
        C = 64; S = 200;
        logits  = plog + (size_t)b * TMAX * 64;
        targets = ptgt + b * 200;
        ilen = pil[b]; tlen = ptl[b];
    }
    const int L     = 2 * S + 1;
    const int Teff  = min(TMAX, max(ilen, 1));
    const int rlast = Teff - 1;
    const bool warpLive = (128 * wid < L);

    // ---------- zero handshake ring (sentinel = lo32 == 0) ----------
    {
        uint4 z = make_uint4(0, 0, 0, 0);
        uint4* r4 = reinterpret_cast<uint4*>(sRing);
        for (int i = tid; i < 4 * TMAX / 2; i += NT) r4[i] = z;
    }

    // ---------- Phase 1: log2 softmax denominators ----------
    for (int t = tid; t < Teff; t += NT) {
        const float* row = logits + (size_t)t * C;
        float s = 0.f;
        for (int k = 0; k < C; k += 4) {
            float4 v = *reinterpret_cast<const float4*>(row + k);
            s += ex2(v.x * LOG2E) + ex2(v.y * LOG2E)
               + ex2(v.z * LOG2E) + ex2(v.w * LOG2E);
        }
        sD[t] = lg2(s);
    }
    __syncthreads();   // sD + zeroed ring visible to all warps

    // ---------- Per-thread slot setup: l = 4*tid + {0,1,2,3} ----------
    const int  l0 = 4 * tid;
    const int  j1  = min(2 * tid,     S - 1);
    const int  j1m = max(2 * tid - 1, 0);
    const int  j3  = min(2 * tid + 1, S - 1);
    const int  ext1 = targets[j1];
    const int  ext3 = targets[j3];
    const bool skip1 = (tid >= 1) && (ext1 != targets[j1m]);
    const bool skip3 = (ext3 != ext1);

    // ---------- alpha init (t = 0) ----------
    float m0 = 1.f, m1 = 1.f, m2 = 1.f, m3 = 1.f;
    int   e0 = EDEAD, e1 = EDEAD, e2 = EDEAD, e3 = EDEAD;
    if (tid == 0) {
        float a = ex2(clamplp(fmaf(logits[0],    LOG2E, -sD[0])));
        int bb = __float_as_int(a);
        e0 = (bb >> 23) - 127; m0 = __int_as_float((bb & 0x007FFFFF) | 0x3F800000);
        a = ex2(clamplp(fmaf(logits[ext1], LOG2E, -sD[0])));
        bb = __float_as_int(a);
        e1 = (bb >> 23) - 127; m1 = __int_as_float((bb & 0x007FFFFF) | 0x3F800000);
    }

    const unsigned rbase = (unsigned)__cvta_generic_to_shared(sRing);
    unsigned ringW = rbase + (unsigned)(wid * TMAX) * 8u;        // slot t: +8t
    unsigned ringR = rbase + (unsigned)((wid - 1) * TMAX) * 8u;  // slot t-1

    // publish initial slot-3 state (t = 0)
    if (lane == 31) {
        asm volatile("st.volatile.shared.v2.u32 [%0], {%1,%2};"
                     :: "r"(ringW), "r"(__float_as_uint(m3)), "r"((unsigned)e3));
    }

    if (warpLive && Teff > 1) {
        // ---------- private staging init ----------
        const int k0 = lane, k1 = lane + 32;
        const bool u0 = (k0 < C), u1 = (k1 < C);
        float exv0 = 0.f, exv1 = 0.f;            // probs for row t+2 (pending STS)
        float gA0 = 0.f, gA1 = 0.f, gB0 = 0.f, gB1 = 0.f, gC0 = 0.f, gC1 = 0.f;

        {
            int r1 = min(1, rlast), r2 = min(2, rlast);
            int r3 = min(3, rlast), r4 = min(4, rlast), r5 = min(5, rlast);
            if (u0) {
                sMy[wid][1][k0] = ex2(clamplp(fmaf(logits[(size_t)r1 * C + k0],
                                                   LOG2E, -sD[r1])));
                exv0 = ex2(clamplp(fmaf(logits[(size_t)r2 * C + k0], LOG2E, -sD[r2])));
                gA0 = logits[(size_t)r3 * C + k0];
                gB0 = logits[(size_t)r4 * C + k0];
                gC0 = logits[(size_t)r5 * C + k0];
            }
            if (u1) {
                sMy[wid][1][k1] = ex2(clamplp(fmaf(logits[(size_t)r1 * C + k1],
                                                   LOG2E, -sD[r1])));
                exv1 = ex2(clamplp(fmaf(logits[(size_t)r2 * C + k1], LOG2E, -sD[r2])));
                gA1 = logits[(size_t)r3 * C + k1];
                gB1 = logits[(size_t)r4 * C + k1];
                gC1 = logits[(size_t)r5 * C + k1];
            }
        }
        __syncwarp();
        float pb = sMy[wid][1][0];
        float p1 = sMy[wid][1][ext1];
        float p3 = sMy[wid][1][ext3];

        unsigned rw = ringW + 8;   // write slot t
        unsigned rr = ringR;       // read slot t-1

        // ---------- Phase 2: barrier-free forward scan ----------
        for (int t = 1; t < Teff; ++t) {
            // 1. slot 3 first (no incoming dependency) -> publish ASAP
            float o3m; int o3e;
            upd3(m3, e3, m2, e2, m1, skip3 ? e1 : EDEAD, p3, o3m, o3e);
            if (lane == 31) {
                asm volatile("st.volatile.shared.v2.u32 [%0], {%1,%2};"
                             :: "r"(rw), "r"(__float_as_uint(o3m)), "r"((unsigned)o3e));
            }

            // 2. private staging: STS row t+1, compute row t+2, LDG row t+5
            {
                int t2 = min(t + 2, rlast);
                int t5 = min(t + 5, rlast);
                float d2 = sD[t2];
                const int bq = (t + 1) & 1;
                if (u0) {
                    sMy[wid][bq][k0] = exv0;
                    exv0 = ex2(clamplp(fmaf(gA0, LOG2E, -d2)));
                    gA0 = gB0; gB0 = gC0;
                    gC0 = logits[(size_t)t5 * C + k0];
                }
                if (u1) {
                    sMy[wid][bq][k1] = exv1;
                    exv1 = ex2(clamplp(fmaf(gA1, LOG2E, -d2)));
                    gA1 = gB1; gB1 = gC1;
                    gC1 = logits[(size_t)t5 * C + k1];
                }
            }

            // 3. left neighbor's OLD slot-3: shuffle + broadcast poll
            float nm3 = __shfl_up_sync(0xffffffffu, m3, 1);
            int   ne3 = __shfl_up_sync(0xffffffffu, e3, 1);
            if (wid > 0) {
                unsigned lo, hi;
                do {
                    asm volatile("ld.volatile.shared.v2.u32 {%0,%1}, [%2];"
                                 : "=r"(lo), "=r"(hi) : "r"(rr));
                } while (lo == 0u);
                if (lane == 0) { nm3 = __uint_as_float(lo); ne3 = (int)hi; }
            } else if (lane == 0) { nm3 = 1.f; ne3 = EDEAD; }

            // 4. slots 0..2
            float o0m, o1m, o2m; int o0e, o1e, o2e;
            upd2(m0, e0, nm3, ne3, pb, o0m, o0e);
            upd3(m1, e1, m0, e0, nm3, skip1 ? ne3 : EDEAD, p1, o1m, o1e);
            upd2(m2, e2, m1, e1, pb, o2m, o2e);
            m0 = o0m; e0 = o0e; m1 = o1m; e1 = o1e;
            m2 = o2m; e2 = o2e; m3 = o3m; e3 = o3e;

            // 5. prob prefetch for t+1 from own freshly staged row
            __syncwarp();
            {
                const float* rowp = sMy[wid][(t + 1) & 1];
                pb = rowp[0]; p1 = rowp[ext1]; p3 = rowp[ext3];
            }
            rw += 8; rr += 8;
        }
    }

    // ---------- publish finals ----------
    sFm[l0] = m0;     sFe[l0] = e0;
    sFm[l0 + 1] = m1; sFe[l0 + 1] = e1;
    sFm[l0 + 2] = m2; sFe[l0 + 2] = e2;
    sFm[l0 + 3] = m3; sFe[l0 + 3] = e3;
    __syncthreads();

    // ---------- loss + fused deterministic reduction ----------
    if (tid == 0) {
        const int iL = 2 * tlen - 1, iB = 2 * tlen;
        int   eL = sFe[iL], eB = sFe[iB];
        float mL = sFm[iL], mB = sFm[iB];
        int   em = max(eL, eB);
        float ss = mL * pow2c(eL + 127 - em) + mB * pow2c(eB + 127 - em);
        float loss = -((float)em + lg2(ss)) * LN2;
        if (em < -(1 << 27)) loss = 0.f;      // unreachable => inf => zeroed
        if (!(loss <= 1e29f)) loss = 0.f;     // zero_infinity / NaN
        g_partial[blockIdx.x] = loss / (float)tlen * (1.0f / BATCH);
        __threadfence();
        unsigned tk = atomicAdd(&g_count, 1u);
        sLast = (tk == 63u);
    }
    __syncthreads();
    if (sLast && tid == 0) {
        __threadfence();
        float s = 0.f;
        #pragma unroll
        for (int i = 0; i < 64; ++i) {
            float v;
            asm volatile("ld.global.cg.f32 %0, [%1];" : "=f"(v) : "l"(g_partial + i));
            s += v;
        }
        out[0] = s;
        g_count = 0;   // reset for graph replay
    }
}

extern "C" void kernel_launch(void* const* d_in, const int* in_sizes, int n_in,
                              void* d_out, int out_size)
{
    const float* elog = (const float*)d_in[0];
    const float* plog = (const float*)d_in[1];
    const int*   etgt = (const int*)d_in[2];
    const int*   ptgt = (const int*)d_in[3];
    const int*   eil  = (const int*)d_in[4];
    const int*   pil  = (const int*)d_in[5];
    const int*   etl  = (const int*)d_in[6];
    const int*   ptl  = (const int*)d_in[7];
    float* out = (float*)d_out;

    cudaFuncSetAttribute(ctc_forward_kernel,
                         cudaFuncAttributeMaxDynamicSharedMemorySize, DYNSMEM);
    ctc_forward_kernel<<<64, NT, DYNSMEM>>>(elog, plog, etgt, ptgt,
                                            eil, pil, etl, ptl, out);
}

// round 14
// speedup vs baseline: 1.1522x; 1.1522x over previous
#include <cuda_runtime.h>
#include <cuda_bf16.h>

// CTC forward, two tasks (PyTorch semantics: blank=0, mean of loss/target_len,
// zero_infinity). One block per (task, batch) = 64 blocks x 128 threads.
//
// R9 skeleton (4 warps, 1 __syncthreads per timestep, shared prob staging)
// with BLOCK-FLOAT-PER-THREAD alpha state: each thread owns 4 consecutive
// extended-target positions as 4 plain fp32 mantissas sharing ONE int32
// exponent (max mantissa renormalized to [1,2) each step; dead slot = 0).
// Intra-thread recurrence terms need no alignment -> plain FADD/FMUL; only
// the neighbor block (left thread's slot 3) needs one exponent alignment.
// Probs are staged pre-exponentiated (linear domain) by tid<C stagers, so
// consumer threads execute ZERO MUFU ops in the scan loop.

#define LOG2E 1.4426950408889634f
#define LN2   0.6931471805599453f
#define BATCH 32
#define TMAX  2000
#define NT    128
#define EMIN  (-(1 << 28))

static __device__ float        g_partial[64];
static __device__ unsigned int g_count = 0;

__device__ __forceinline__ float ex2(float x) {
    float y; asm("ex2.approx.f32 %0, %1;" : "=f"(y) : "f"(x)); return y;
}
__device__ __forceinline__ float lg2(float x) {
    float y; asm("lg2.approx.f32 %0, %1;" : "=f"(y) : "f"(x)); return y;
}
__device__ __forceinline__ float pow2c(int dp127) {   // 2^d, clamped both ends
    return __int_as_float(min(max(dp127, 0), 254) << 23);
}
__device__ __forceinline__ float clamplp(float x) {   // keep ex2 output normal
    return fminf(fmaxf(x, -120.f), 0.f);
}

__global__ void __launch_bounds__(NT, 1)
ctc_forward_kernel(const float* __restrict__ elog, const float* __restrict__ plog,
                   const int* __restrict__ etgt, const int* __restrict__ ptgt,
                   const int* __restrict__ eil,  const int* __restrict__ pil,
                   const int* __restrict__ etl,  const int* __restrict__ ptl,
                   float* __restrict__ out)
{
    __shared__ float sD[TMAX];        // log2 softmax denominator per timestep
    __shared__ float sStage[2][64];   // staged LINEAR prob rows (ex2 applied)
    __shared__ uint2 sBnd[2][4];      // per-warp lane31 (m3, e), double-buffered
    __shared__ float sFm[NT * 4];
    __shared__ int   sFe[NT * 4];
    __shared__ int   sLast;

    const int task = blockIdx.x >> 5;   // 0 = error (C=4), 1 = phoneme (C=64)
    const int b    = blockIdx.x & 31;
    const int tid  = threadIdx.x;
    const int lane = tid & 31;
    const int wid  = tid >> 5;

    const float* logits;
    const int*   targets;
    int C, S, ilen, tlen;
    if (task == 0) {
        C = 4;  S = 50;
        logits  = elog + (size_t)b * TMAX * 4;
        targets = etgt + b * 50;
        ilen = eil[b]; tlen = etl[b];
    } else {
        C = 64; S = 200;
        logits  = plog + (size_t)b * TMAX * 64;
        targets = ptgt + b * 200;
        ilen = pil[b]; tlen = ptl[b];
    }
    const int Teff  = min(TMAX, max(ilen, 1));
    const int rlast = Teff - 1;

    // ---------- Phase 1: log2 softmax denominators ----------
    for (int t = tid; t < Teff; t += NT) {
        const float* row = logits + (size_t)t * C;
        float s = 0.f;
        for (int k = 0; k < C; k += 4) {
            float4 v = *reinterpret_cast<const float4*>(row + k);
            s += ex2(v.x * LOG2E) + ex2(v.y * LOG2E)
               + ex2(v.z * LOG2E) + ex2(v.w * LOG2E);
        }
        sD[t] = lg2(s);
    }
    __syncthreads();

    // ---------- Per-thread slot setup: l = 4*tid + {0,1,2,3} ----------
    const int  l0 = 4 * tid;
    const int  j1  = min(2 * tid,     S - 1);
    const int  j1m = max(2 * tid - 1, 0);
    const int  j3  = min(2 * tid + 1, S - 1);
    const int  ext1 = targets[j1];
    const int  ext3 = targets[j3];
    const bool skip1 = (tid >= 1) && (ext1 != targets[j1m]);
    const bool skip3 = (ext3 != ext1);

    // ---------- block-float state init (t = 0) ----------
    float m0 = 0.f, m1 = 0.f, m2 = 0.f, m3 = 0.f;
    int   e  = 0;
    bool  live = false;
    if (tid == 0) {
        m0 = ex2(clamplp(fmaf(logits[0],    LOG2E, -sD[0])));
        m1 = ex2(clamplp(fmaf(logits[ext1], LOG2E, -sD[0])));
        live = true;
    }
    if (lane == 31) sBnd[0][wid] = make_uint2(__float_as_uint(m3), (unsigned)e);

    // Stage row 1 (linear probs); prefetch row 2 logits.
    float gpre = 0.f;
    if (tid < C) {
        int r1 = min(1, rlast);
        sStage[1][tid] = ex2(clamplp(fmaf(logits[(size_t)r1 * C + tid], LOG2E,
                                          -sD[r1])));
        gpre = logits[(size_t)min(2, rlast) * C + tid];
    }
    __syncthreads();

    float pb = sStage[1][0];
    float p1 = sStage[1][ext1];
    float p3 = sStage[1][ext3];

    // ---------- Phase 2: forward scan, 1 step per barrier ----------
    for (int t = 1; t < Teff; ++t) {
        const int q  = (t + 1) & 1;   // stage buffer for row t+1
        const int br = (t - 1) & 1;   // sBnd buffer holding state @ t-1
        const int bw = t & 1;         // sBnd buffer to write state @ t

        // Stagers: convert row t+1 to linear probs; prefetch row t+2 logits.
        if (tid < C) {
            if (t + 1 < Teff)
                sStage[q][tid] = ex2(clamplp(fmaf(gpre, LOG2E, -sD[t + 1])));
            if (t + 2 < Teff)
                gpre = logits[(size_t)(t + 2) * C + tid];
        }

        // Left thread's OLD slot-3 block (m3, e).
        float nm3 = __shfl_up_sync(0xffffffffu, m3, 1);
        int   ne  = __shfl_up_sync(0xffffffffu, e,  1);
        if (lane == 0) {
            if (wid > 0) {
                uint2 v = sBnd[br][wid - 1];
                nm3 = __uint_as_float(v.x); ne = (int)v.y;
            } else { nm3 = 0.f; ne = EMIN; }
        }

        // Common exponent basis (liveness-aware) + two alignments.
        int eo = live         ? e  : EMIN;
        int en = (nm3 > 0.f)  ? ne : EMIN;
        int em = max(eo, en);
        float sco = pow2c(e  - em + 127);
        float scn = pow2c(ne - em + 127);
        float a0 = m0 * sco, a1 = m1 * sco, a2 = m2 * sco, a3 = m3 * sco;
        float an = nm3 * scn;

        // Plain-float recurrence (all terms share exponent em now).
        float n0 = pb * (a0 + an);
        float n1 = p1 * ((a1 + a0) + (skip1 ? an : 0.f));
        float n2 = pb * (a2 + a1);
        float n3 = p3 * ((a3 + a2) + (skip3 ? a1 : 0.f));

        // Renormalize block: max mantissa -> [1,2).
        float mm = fmaxf(fmaxf(n0, n1), fmaxf(n2, n3));
        int bb = __float_as_int(mm);
        live = (bb != 0);
        int sh = live ? ((bb >> 23) - 127) : 0;
        float rs = __int_as_float((127 - sh) << 23);
        m0 = n0 * rs; m1 = n1 * rs; m2 = n2 * rs; m3 = n3 * rs;
        e  = em + sh;

        if (lane == 31)
            sBnd[bw][wid] = make_uint2(__float_as_uint(m3), (unsigned)e);

        __syncthreads();

        // Prefetch probs for step t+1 (row already staged; off critical path).
        if (t + 1 < Teff) {
            const float* rowp = sStage[q];
            pb = rowp[0]; p1 = rowp[ext1]; p3 = rowp[ext3];
        }
    }

    // ---------- publish finals (per-slot mantissa + shared exponent) ----------
    sFm[l0] = m0;     sFe[l0] = e;
    sFm[l0 + 1] = m1; sFe[l0 + 1] = e;
    sFm[l0 + 2] = m2; sFe[l0 + 2] = e;
    sFm[l0 + 3] = m3; sFe[l0 + 3] = e;
    __syncthreads();

    // ---------- loss + fused deterministic reduction ----------
    if (tid == 0) {
        const int iL = 2 * tlen - 1, iB = 2 * tlen;
        float mL = sFm[iL], mB = sFm[iB];
        int   eL = (mL > 0.f) ? sFe[iL] : EMIN;
        int   eB = (mB > 0.f) ? sFe[iB] : EMIN;
        int   em = max(eL, eB);
        float ss = mL * pow2c(eL + 127 - em) + mB * pow2c(eB + 127 - em);
        float loss;
        if (em <= EMIN / 2 || ss <= 0.f) loss = 0.f;   // unreachable => inf => 0
        else loss = -((float)em + lg2(ss)) * LN2;
        if (!(loss <= 1e29f)) loss = 0.f;              // zero_infinity / NaN
        g_partial[blockIdx.x] = loss / (float)tlen * (1.0f / BATCH);
        __threadfence();
        unsigned tk = atomicAdd(&g_count, 1u);
        sLast = (tk == 63u);
    }
    __syncthreads();
    if (sLast && tid == 0) {
        __threadfence();
        float s = 0.f;
        #pragma unroll
        for (int i = 0; i < 64; ++i) {
            float v;
            asm volatile("ld.global.cg.f32 %0, [%1];" : "=f"(v) : "l"(g_partial + i));
            s += v;
        }
        out[0] = s;
        g_count = 0;   // reset for graph replay
    }
}

extern "C" void kernel_launch(void* const* d_in, const int* in_sizes, int n_in,
                              void* d_out, int out_size)
{
    const float* elog = (const float*)d_in[0];
    const float* plog = (const float*)d_in[1];
    const int*   etgt = (const int*)d_in[2];
    const int*   ptgt = (const int*)d_in[3];
    const int*   eil  = (const int*)d_in[4];
    const int*   pil  = (const int*)d_in[5];
    const int*   etl  = (const int*)d_in[6];
    const int*   ptl  = (const int*)d_in[7];
    float* out = (float*)d_out;

    ctc_forward_kernel<<<64, NT>>>(elog, plog, etgt, ptgt,
                                   eil, pil, etl, ptl, out);
}